// round 8
// baseline (speedup 1.0000x reference)
#include <cuda_runtime.h>
#include <cstdint>

#define NUM_SEG 100000
#define DIM 32
#define TPB 256
#define ROWS_PER_BLK 256
#define TILE_BYTES (ROWS_PER_BLK * DIM * 4)   // 32 KB
#define NCTAS 444                              // 3 CTAs/SM * 148 SMs

// Scratch: per-segment counts (allocation-free rule => __device__ global)
__device__ float g_counts[NUM_SEG];

__device__ __forceinline__ uint32_t smem_u32(const void* p) {
    uint32_t a;
    asm("{ .reg .u64 t; cvta.to.shared.u64 t, %1; cvt.u32.u64 %0, t; }" : "=r"(a) : "l"(p));
    return a;
}

// Persistent, double-buffered TMA pipeline:
//   bulk-in(tile k+1) overlaps bulk-reduce(tile k); count atomics issued while
//   the TMA load is in flight. SM-side work ~nothing; pipeline = TMA engine +
//   L2 atomic ALU, continuously fed.
__global__ void __launch_bounds__(TPB) scatter_kernel(
    const float* __restrict__ x,
    const int* __restrict__ index,
    float* __restrict__ out,
    int nrows, int ntiles)
{
    __shared__ __align__(128) float tile[2][ROWS_PER_BLK * DIM];  // 2 x 32 KB
    __shared__ __align__(8) unsigned long long mbar[2];

    int t = threadIdx.x;
    uint32_t mb0 = smem_u32(&mbar[0]);
    uint32_t mb1 = smem_u32(&mbar[1]);

    if (t == 0) {
        asm volatile("mbarrier.init.shared.b64 [%0], 1;" :: "r"(mb0) : "memory");
        asm volatile("mbarrier.init.shared.b64 [%0], 1;" :: "r"(mb1) : "memory");
    }
    __syncthreads();

    int phase[2] = {0, 0};
    int it = 0;
    for (int tile_id = blockIdx.x; tile_id < ntiles; tile_id += NCTAS, it++) {
        int b = it & 1;
        uint32_t mb = b ? mb1 : mb0;
        int row0 = tile_id * ROWS_PER_BLK;
        int row = row0 + t;
        bool full_tile = (row0 + ROWS_PER_BLK) <= nrows;

        // Backpressure: my reduce group from 2 iterations ago (same buffer)
        // must have finished reading smem before the producer overwrites it.
        if (it >= 2)
            asm volatile("cp.async.bulk.wait_group 1;" ::: "memory");
        __syncthreads();

        if (full_tile) {
            if (t == 0) {
                uint32_t dst = smem_u32(tile[b]);
                const float* src = x + (long long)row0 * DIM;
                asm volatile("mbarrier.arrive.expect_tx.shared.b64 _, [%0], %1;"
                             :: "r"(mb), "r"(TILE_BYTES) : "memory");
                asm volatile(
                    "cp.async.bulk.shared::cta.global.mbarrier::complete_tx::bytes "
                    "[%0], [%1], %2, [%3];"
                    :: "r"(dst), "l"(src), "r"(TILE_BYTES), "r"(mb) : "memory");
            }
        } else {
            // Tail tile: per-thread loads (generic proxy).
            for (int k = 0; k < 8; k++) {
                int local = t + k * TPB;
                int r = row0 + (local >> 3);
                if (r < nrows)
                    ((float4*)tile[b])[local] =
                        ((const float4*)x)[(long long)r * 8 + (local & 7)];
            }
            __syncthreads();
            asm volatile("fence.proxy.async.shared::cta;" ::: "memory");
        }

        // Overlap with the in-flight TMA load: index read + count atomic.
        int seg = -1;
        if (row < nrows) {
            seg = index[row];
            if ((unsigned)seg >= NUM_SEG) seg = -1;
            if (seg >= 0) atomicAdd(&g_counts[seg], 1.0f);
        }

        if (full_tile) {
            int p = phase[b];
            asm volatile(
                "{\n\t.reg .pred P;\n"
                "WAIT_%=:\n\t"
                "mbarrier.try_wait.parity.shared.b64 P, [%0], %1, 0x989680;\n\t"
                "@!P bra WAIT_%=;\n\t}"
                :: "r"(mb), "r"(p) : "memory");
            phase[b] = p ^ 1;
        }

        if (seg >= 0) {
            uint32_t saddr = smem_u32(&tile[b][t * DIM]);
            float* gdst = out + (long long)seg * DIM;
            asm volatile(
                "cp.reduce.async.bulk.global.shared::cta.bulk_group.add.f32 [%0], [%1], %2;"
                :: "l"(gdst), "r"(saddr), "r"(DIM * 4) : "memory");
        }
        asm volatile("cp.async.bulk.commit_group;" ::: "memory");
    }
    // Drain all outstanding reduce groups before smem is torn down.
    asm volatile("cp.async.bulk.wait_group 0;" ::: "memory");
}

// Grid-stride divide, 2 float4 per thread iteration for MLP.
__global__ void __launch_bounds__(TPB) divide_kernel(float4* __restrict__ out4, int total4) {
    int stride = gridDim.x * blockDim.x * 2;
    for (int i = (blockIdx.x * blockDim.x + threadIdx.x) * 2; i < total4; i += stride) {
        float c0 = __ldg(&g_counts[i >> 3]);
        float4 v0 = out4[i];
        int j = i + 1;
        float4 v1; float c1 = 1.0f;
        bool has2 = (j < total4);
        if (has2) { c1 = __ldg(&g_counts[j >> 3]); v1 = out4[j]; }
        float r0 = __frcp_rn(fmaxf(c0, 1.0f));
        v0.x *= r0; v0.y *= r0; v0.z *= r0; v0.w *= r0;
        out4[i] = v0;
        if (has2) {
            float r1 = __frcp_rn(fmaxf(c1, 1.0f));
            v1.x *= r1; v1.y *= r1; v1.z *= r1; v1.w *= r1;
            out4[j] = v1;
        }
    }
}

extern "C" void kernel_launch(void* const* d_in, const int* in_sizes, int n_in,
                              void* d_out, int out_size) {
    const float* x = (const float*)d_in[0];
    const int* index = (const int*)d_in[1];
    float* out = (float*)d_out;

    int nrows = in_sizes[1];   // 4,000,000
    int total = out_size;      // NUM_SEG * DIM

    void* counts_ptr = nullptr;
    cudaGetSymbolAddress(&counts_ptr, g_counts);
    cudaMemsetAsync(out, 0, (size_t)total * sizeof(float), 0);
    cudaMemsetAsync(counts_ptr, 0, (size_t)NUM_SEG * sizeof(float), 0);

    int ntiles = (nrows + ROWS_PER_BLK - 1) / ROWS_PER_BLK;
    scatter_kernel<<<NCTAS, TPB>>>(x, index, out, nrows, ntiles);

    int total4 = total / 4;
    divide_kernel<<<592, TPB>>>((float4*)out, total4);
}

// round 9
// speedup vs baseline: 1.1387x; 1.1387x over previous
#include <cuda_runtime.h>
#include <cstdint>

#define NUM_SEG 100000
#define DIM 32
#define TPB 256
#define ROWS_PER_BLK 256
#define TILE_BYTES (ROWS_PER_BLK * DIM * 4)   // 32 KB

// Scratch: per-segment counts (allocation-free rule => __device__ global)
__device__ float g_counts[NUM_SEG];

__device__ __forceinline__ uint32_t smem_u32(const void* p) {
    uint32_t a;
    asm("{ .reg .u64 t; cvta.to.shared.u64 t, %1; cvt.u32.u64 %0, t; }" : "=r"(a) : "l"(p));
    return a;
}

// R7 structure (best so far): one CTA per 256-row tile, bulk-in the tile via a
// single 32 KB cp.async.bulk, then one 128 B cp.reduce.async.bulk per row.
// Change vs R7: the index load + count atomic are issued BEFORE the mbarrier
// wait so they overlap the in-flight TMA load instead of extending the
// critical path. Cross-CTA overlap comes from 7 co-resident CTAs/SM.
__global__ void __launch_bounds__(TPB) scatter_kernel(
    const float* __restrict__ x,
    const int* __restrict__ index,
    float* __restrict__ out,
    int nrows)
{
    __shared__ __align__(128) float tile[ROWS_PER_BLK * DIM];  // 32 KB
    __shared__ __align__(8) unsigned long long mbar;

    int t = threadIdx.x;
    int row0 = blockIdx.x * ROWS_PER_BLK;
    int row = row0 + t;
    bool full_tile = (row0 + ROWS_PER_BLK) <= nrows;
    uint32_t mb = smem_u32(&mbar);

    if (full_tile) {
        if (t == 0) {
            asm volatile("mbarrier.init.shared.b64 [%0], 1;" :: "r"(mb) : "memory");
        }
        __syncthreads();
        if (t == 0) {
            uint32_t dst = smem_u32(tile);
            const float* src = x + (long long)row0 * DIM;
            asm volatile("mbarrier.arrive.expect_tx.shared.b64 _, [%0], %1;"
                         :: "r"(mb), "r"(TILE_BYTES) : "memory");
            asm volatile(
                "cp.async.bulk.shared::cta.global.mbarrier::complete_tx::bytes "
                "[%0], [%1], %2, [%3];"
                :: "r"(dst), "l"(src), "r"(TILE_BYTES), "r"(mb) : "memory");
        }

        // Overlap with the in-flight TMA load: index read + count atomic.
        int seg = index[row];
        if ((unsigned)seg >= NUM_SEG) seg = -1;
        if (seg >= 0) atomicAdd(&g_counts[seg], 1.0f);

        // Wait for the bulk load (parity 0).
        asm volatile(
            "{\n\t.reg .pred P;\n"
            "WAIT_%=:\n\t"
            "mbarrier.try_wait.parity.shared.b64 P, [%0], 0, 0x989680;\n\t"
            "@!P bra WAIT_%=;\n\t}"
            :: "r"(mb) : "memory");

        if (seg >= 0) {
            uint32_t saddr = smem_u32(&tile[t * DIM]);
            float* gdst = out + (long long)seg * DIM;
            asm volatile(
                "cp.reduce.async.bulk.global.shared::cta.bulk_group.add.f32 [%0], [%1], %2;"
                :: "l"(gdst), "r"(saddr), "r"(DIM * 4) : "memory");
        }
    } else {
        // Tail tile: per-thread loads (generic proxy).
        for (int k = 0; k < 8; k++) {
            int local = t + k * TPB;
            int r = row0 + (local >> 3);
            if (r < nrows)
                ((float4*)tile)[local] = ((const float4*)x)[(long long)r * 8 + (local & 7)];
        }
        __syncthreads();
        asm volatile("fence.proxy.async.shared::cta;" ::: "memory");

        if (row < nrows) {
            int seg = index[row];
            if ((unsigned)seg < NUM_SEG) {
                atomicAdd(&g_counts[seg], 1.0f);
                uint32_t saddr = smem_u32(&tile[t * DIM]);
                float* gdst = out + (long long)seg * DIM;
                asm volatile(
                    "cp.reduce.async.bulk.global.shared::cta.bulk_group.add.f32 [%0], [%1], %2;"
                    :: "l"(gdst), "r"(saddr), "r"(DIM * 4) : "memory");
            }
        }
    }
    // Drain bulk ops before CTA exit (smem is read asynchronously).
    asm volatile("cp.async.bulk.commit_group;" ::: "memory");
    asm volatile("cp.async.bulk.wait_group 0;" ::: "memory");
}

// Divide with MLP=4: four independent float4 streams per thread, all loads
// issued before any arithmetic/stores.
__global__ void __launch_bounds__(TPB) divide_kernel(float4* __restrict__ out4, int total4) {
    int base = blockIdx.x * (TPB * 4) + threadIdx.x;
    int i0 = base;
    int i1 = base + TPB;
    int i2 = base + TPB * 2;
    int i3 = base + TPB * 3;

    float4 v0, v1, v2, v3;
    float c0 = 1.f, c1 = 1.f, c2 = 1.f, c3 = 1.f;
    bool b0 = i0 < total4, b1 = i1 < total4, b2 = i2 < total4, b3 = i3 < total4;

    if (b0) { v0 = out4[i0]; c0 = __ldg(&g_counts[i0 >> 3]); }
    if (b1) { v1 = out4[i1]; c1 = __ldg(&g_counts[i1 >> 3]); }
    if (b2) { v2 = out4[i2]; c2 = __ldg(&g_counts[i2 >> 3]); }
    if (b3) { v3 = out4[i3]; c3 = __ldg(&g_counts[i3 >> 3]); }

    if (b0) { float r = __frcp_rn(fmaxf(c0, 1.f)); v0.x*=r; v0.y*=r; v0.z*=r; v0.w*=r; out4[i0]=v0; }
    if (b1) { float r = __frcp_rn(fmaxf(c1, 1.f)); v1.x*=r; v1.y*=r; v1.z*=r; v1.w*=r; out4[i1]=v1; }
    if (b2) { float r = __frcp_rn(fmaxf(c2, 1.f)); v2.x*=r; v2.y*=r; v2.z*=r; v2.w*=r; out4[i2]=v2; }
    if (b3) { float r = __frcp_rn(fmaxf(c3, 1.f)); v3.x*=r; v3.y*=r; v3.z*=r; v3.w*=r; out4[i3]=v3; }
}

extern "C" void kernel_launch(void* const* d_in, const int* in_sizes, int n_in,
                              void* d_out, int out_size) {
    const float* x = (const float*)d_in[0];
    const int* index = (const int*)d_in[1];
    float* out = (float*)d_out;

    int nrows = in_sizes[1];   // 4,000,000
    int total = out_size;      // NUM_SEG * DIM

    void* counts_ptr = nullptr;
    cudaGetSymbolAddress(&counts_ptr, g_counts);
    cudaMemsetAsync(out, 0, (size_t)total * sizeof(float), 0);
    cudaMemsetAsync(counts_ptr, 0, (size_t)NUM_SEG * sizeof(float), 0);

    int sb = (nrows + ROWS_PER_BLK - 1) / ROWS_PER_BLK;
    scatter_kernel<<<sb, TPB>>>(x, index, out, nrows);

    int total4 = total / 4;
    int db = (total4 + TPB * 4 - 1) / (TPB * 4);
    divide_kernel<<<db, TPB>>>((float4*)out, total4);
}